// round 14
// baseline (speedup 1.0000x reference)
#include <cuda_runtime.h>
#include <cuda_bf16.h>
#include <cstdint>

// ---------------- problem constants ----------------
#define NB      2
#define SEQ     2048
#define DIMM    768
#define DINNER  1536
#define DSTATE  16
#define DCONV   4
#define DTRANK  48
#define MROWS   (NB*SEQ)            // 4096
#define DBLCOLS 80
#define VOCAB   32000
#define NCHUNK  32
#define LCHUNK  (SEQ/NCHUNK)        // 64
#define NCH     (NB*DINNER)         // 3072
#define LOG2E   1.4426950408889634f
#define KSPLIT  4

typedef __nv_bfloat16 bf16;

// ---------------- fp32 scratch ----------------
__device__ float g_x   [MROWS * DIMM];
__device__ float g_xz  [MROWS * 2 * DINNER];
__device__ float g_xssm[MROWS * DINNER];
__device__ float g_dbl [MROWS * DBLCOLS];
__device__ float g_dblp[KSPLIT * MROWS * DBLCOLS];
__device__ float g_dt  [MROWS * DINNER];
__device__ float g_hend  [NCHUNK * NCH * DSTATE];
__device__ float g_pend  [NCHUNK * NCH * DSTATE];
__device__ float g_hentry[NCHUNK * NCH * DSTATE];

// ---------------- bf16 hi/lo scratch ----------------
__device__ __align__(16) bf16 g_xhi   [MROWS * DIMM],   g_xlo   [MROWS * DIMM];
__device__ __align__(16) bf16 g_xssmhi[MROWS * DINNER], g_xssmlo[MROWS * DINNER];
__device__ __align__(16) bf16 g_dblhi [MROWS * DBLCOLS],g_dbllo [MROWS * DBLCOLS];
__device__ __align__(16) bf16 g_yhi   [MROWS * DINNER], g_ylo   [MROWS * DINNER];
__device__ __align__(16) bf16 g_xlnhi [MROWS * DIMM],   g_xlnlo [MROWS * DIMM];
__device__ __align__(16) bf16 g_winhi [4 * 2 * DINNER * DIMM],  g_winlo [4 * 2 * DINNER * DIMM];
__device__ __align__(16) bf16 g_wxhi  [4 * DBLCOLS * DINNER],   g_wxlo  [4 * DBLCOLS * DINNER];
__device__ __align__(16) bf16 g_wdthi [4 * DINNER * DTRANK],    g_wdtlo [4 * DINNER * DTRANK];
__device__ __align__(16) bf16 g_wouthi[4 * DIMM * DINNER],      g_woutlo[4 * DIMM * DINNER];
__device__ __align__(16) bf16 g_wheadhi[VOCAB * DIMM],          g_wheadlo[VOCAB * DIMM];

// =====================================================================
// low-level helpers
// =====================================================================
__device__ __forceinline__ void cp_async16(uint32_t dst, const void* src, bool pred) {
    int sz = pred ? 16 : 0;
    asm volatile("cp.async.cg.shared.global [%0], [%1], 16, %2;\n"
                 :: "r"(dst), "l"(src), "r"(sz));
}
__device__ __forceinline__ void cp_commit() {
    asm volatile("cp.async.commit_group;\n" ::: "memory");
}
template<int N>
__device__ __forceinline__ void cp_wait() {
    asm volatile("cp.async.wait_group %0;\n" :: "n"(N) : "memory");
}

__device__ __forceinline__ void ldsm_x4(uint32_t* r, uint32_t addr) {
    asm volatile("ldmatrix.sync.aligned.m8n8.x4.shared.b16 {%0,%1,%2,%3}, [%4];"
                 : "=r"(r[0]), "=r"(r[1]), "=r"(r[2]), "=r"(r[3]) : "r"(addr));
}

__device__ __forceinline__ void mma_bf16(float c[4], const uint32_t a[4],
                                         uint32_t b0, uint32_t b1) {
    asm volatile(
        "mma.sync.aligned.m16n8k16.row.col.f32.bf16.bf16.f32 "
        "{%0,%1,%2,%3}, {%4,%5,%6,%7}, {%8,%9}, {%0,%1,%2,%3};\n"
        : "+f"(c[0]), "+f"(c[1]), "+f"(c[2]), "+f"(c[3])
        : "r"(a[0]), "r"(a[1]), "r"(a[2]), "r"(a[3]), "r"(b0), "r"(b1));
}

// =====================================================================
// bf16 hi/lo mma GEMM:  C = (Ahi+Alo) * (Bhi+Blo)^T
// THIS ROUND: 256 threads, 8 warps (4m x 2n), warp tile 32x48
// -> acc 48 regs/thread, ~15 regs slack under the occ-2 cap (128) so
//    ptxas can pipeline ldsm under mma; 16 warps/SM (was 12).
// CTA tile 128x96, 3-stage cp.async pipeline, ONE barrier per K-tile,
// mma.m16n8k16, ldmatrix, 80B-padded rows (conflict-free). occ 2.
// Optional split-K via blockIdx.z.
// EPI 0: C fp32.  EPI 1: softplus(acc + bias[n]).  EPI 2: fp32 + hi/lo split.
// =====================================================================
#define GBK    32
#define ROWB   80          // padded row bytes (conflict-free for ldmatrix)
#define BUFA   10240       // 128 rows * 80
#define BUFB2  7680        // 96 rows * 80
#define SSB    35840       // stage bytes: Ahi,Alo,Bhi,Blo
#define NSTAGE 3
#define SMB    (NSTAGE*SSB)   // 107520
#define NCHUNKS 1792          // (128+128+96+96)*4 16B-chunks per stage

template<int EPI>
__global__ void __launch_bounds__(256, 2) mma_gemm(
    int M, int N, int K,
    const bf16* __restrict__ Ahi, const bf16* __restrict__ Alo, int lda,
    const bf16* __restrict__ Bhi, const bf16* __restrict__ Blo, int ldb,
    const float* __restrict__ bias,
    float* __restrict__ C, int ldc,
    bf16* __restrict__ Chi, bf16* __restrict__ Clo)
{
    extern __shared__ char smem[];
    const uint32_t sb = (uint32_t)__cvta_generic_to_shared(smem);

    const int tid  = threadIdx.x;
    const int lane = tid & 31;
    const int warp = tid >> 5;          // 0..7
    const int wm   = (warp >> 1) * 32;  // warp M offset 0/32/64/96
    const int wn   = (warp & 1) * 48;   // warp N offset 0/48

    const int bm = blockIdx.y * 128;
    const int bn = blockIdx.x * 96;

    const int koff = blockIdx.z * K;
    Ahi += koff; Alo += koff; Bhi += koff; Blo += koff;
    C += (size_t)blockIdx.z * (size_t)M * (size_t)ldc;

    const int la_row = (lane & 7) + ((lane >> 3) & 1) * 8;
    const int la_col = (lane >> 4) * 8;
    const int lb_row = (lane & 7) + (lane >> 4) * 8;
    const int lb_col = ((lane >> 3) & 1) * 8;

    const uint32_t aoff = (uint32_t)(wm + la_row) * ROWB + la_col * 2;
    const uint32_t boff = (uint32_t)(wn + lb_row) * ROWB + lb_col * 2;

    float acc[2][6][4];
    #pragma unroll
    for (int i = 0; i < 2; ++i)
        #pragma unroll
        for (int j = 0; j < 6; ++j)
            #pragma unroll
            for (int q = 0; q < 4; ++q) acc[i][j][q] = 0.f;

    const int ntiles = (K + GBK - 1) / GBK;

    auto fill = [&](int s, int kc) {
        const uint32_t base = sb + (uint32_t)s * SSB;
        const int k0 = kc * GBK;
        #pragma unroll
        for (int i = 0; i < 7; ++i) {
            int c = tid + i * 256;
            if (c >= NCHUNKS) break;
            if (c < 1024) {                     // A: 2 x 512 chunks
                int buf = c >> 9;
                int cc = c & 511;
                int row = cc >> 2, q = cc & 3;
                uint32_t dst = base + (uint32_t)buf * BUFA
                             + (uint32_t)row * ROWB + q * 16;
                bool kok = (k0 + q * 8) < K;
                const bf16* src = buf ? Alo : Ahi;
                cp_async16(dst, src + (size_t)(bm + row) * lda + k0 + q * 8, kok);
            } else {                            // B: 2 x 384 chunks
                int d = c - 1024;
                int buf = d >= 384;
                int cc = d - (buf ? 384 : 0);
                int row = cc >> 2, q = cc & 3;
                uint32_t dst = base + 2 * BUFA + (uint32_t)buf * BUFB2
                             + (uint32_t)row * ROWB + q * 16;
                bool rp = (bn + row) < N;
                bool kok = (k0 + q * 8) < K;
                int r = rp ? (bn + row) : 0;
                const bf16* src = buf ? Blo : Bhi;
                cp_async16(dst, src + (size_t)r * ldb + k0 + q * 8, kok && rp);
            }
        }
    };

    // prologue: 2 stages in flight
    fill(0, 0);
    cp_commit();
    if (ntiles > 1) fill(1, 1);
    cp_commit();

    for (int t = 0; t < ntiles; ++t) {
        const int s = t % NSTAGE;
        cp_wait<1>();             // fill(t) complete
        __syncthreads();          // single barrier per tile
        if (t + 2 < ntiles) fill((t + 2) % NSTAGE, t + 2);
        cp_commit();

        const uint32_t base = sb + (uint32_t)s * SSB;
        #pragma unroll
        for (int ks = 0; ks < 2; ++ks) {
            const uint32_t kb = ks * 32;
            uint32_t ah[2][4], al[2][4], bh[3][4], bl[3][4];
            #pragma unroll
            for (int mt = 0; mt < 2; ++mt) {
                uint32_t a = base + aoff + (uint32_t)mt * (16 * ROWB) + kb;
                ldsm_x4(ah[mt], a);
                ldsm_x4(al[mt], a + BUFA);
            }
            #pragma unroll
            for (int pt = 0; pt < 3; ++pt) {
                uint32_t b = base + 2 * BUFA + boff + (uint32_t)pt * (16 * ROWB) + kb;
                ldsm_x4(bh[pt], b);
                ldsm_x4(bl[pt], b + BUFB2);
            }
            // term 1: hi*hi
            #pragma unroll
            for (int mt = 0; mt < 2; ++mt)
                #pragma unroll
                for (int nt = 0; nt < 6; ++nt) {
                    const int pt = nt >> 1, j = (nt & 1) * 2;
                    mma_bf16(acc[mt][nt], ah[mt], bh[pt][j], bh[pt][j + 1]);
                }
            // term 2: hi*lo
            #pragma unroll
            for (int mt = 0; mt < 2; ++mt)
                #pragma unroll
                for (int nt = 0; nt < 6; ++nt) {
                    const int pt = nt >> 1, j = (nt & 1) * 2;
                    mma_bf16(acc[mt][nt], ah[mt], bl[pt][j], bl[pt][j + 1]);
                }
            // term 3: lo*hi
            #pragma unroll
            for (int mt = 0; mt < 2; ++mt)
                #pragma unroll
                for (int nt = 0; nt < 6; ++nt) {
                    const int pt = nt >> 1, j = (nt & 1) * 2;
                    mma_bf16(acc[mt][nt], al[mt], bh[pt][j], bh[pt][j + 1]);
                }
        }
    }

    __syncthreads();

    // ---- epilogue ----
    #pragma unroll
    for (int mt = 0; mt < 2; ++mt) {
        const int row0 = bm + wm + mt * 16 + (lane >> 2);
        const int row1 = row0 + 8;
        #pragma unroll
        for (int nt = 0; nt < 6; ++nt) {
            const int col = bn + wn + nt * 8 + 2 * (lane & 3);
            if (col >= N) continue;
            float v0 = acc[mt][nt][0], v1 = acc[mt][nt][1];
            float v2 = acc[mt][nt][2], v3 = acc[mt][nt][3];
            if (EPI == 1) {
                float b0 = bias[col], b1 = bias[col + 1];
                v0 += b0; v1 += b1; v2 += b0; v3 += b1;
                v0 = fmaxf(v0, 0.f) + log1pf(__expf(-fabsf(v0)));
                v1 = fmaxf(v1, 0.f) + log1pf(__expf(-fabsf(v1)));
                v2 = fmaxf(v2, 0.f) + log1pf(__expf(-fabsf(v2)));
                v3 = fmaxf(v3, 0.f) + log1pf(__expf(-fabsf(v3)));
            }
            *(float2*)(C + (size_t)row0 * ldc + col) = make_float2(v0, v1);
            *(float2*)(C + (size_t)row1 * ldc + col) = make_float2(v2, v3);
            if (EPI == 2) {
                bf16 h0 = __float2bfloat16(v0), h1 = __float2bfloat16(v1);
                bf16 h2 = __float2bfloat16(v2), h3 = __float2bfloat16(v3);
                bf16 l0 = __float2bfloat16(v0 - __bfloat162float(h0));
                bf16 l1 = __float2bfloat16(v1 - __bfloat162float(h1));
                bf16 l2 = __float2bfloat16(v2 - __bfloat162float(h2));
                bf16 l3 = __float2bfloat16(v3 - __bfloat162float(h3));
                *(__nv_bfloat162*)(Chi + (size_t)row0 * ldc + col) = __nv_bfloat162(h0, h1);
                *(__nv_bfloat162*)(Chi + (size_t)row1 * ldc + col) = __nv_bfloat162(h2, h3);
                *(__nv_bfloat162*)(Clo + (size_t)row0 * ldc + col) = __nv_bfloat162(l0, l1);
                *(__nv_bfloat162*)(Clo + (size_t)row1 * ldc + col) = __nv_bfloat162(l2, l3);
            }
        }
    }
}

// ---------------- weight fp32 -> bf16 hi/lo split ----------------
__device__ __forceinline__ void split4_one(const float* __restrict__ src,
                                           bf16* __restrict__ hi,
                                           bf16* __restrict__ lo, int j)
{
    float4 v = ((const float4*)src)[j];
    bf16 h0 = __float2bfloat16(v.x), h1 = __float2bfloat16(v.y);
    bf16 h2 = __float2bfloat16(v.z), h3 = __float2bfloat16(v.w);
    bf16 l0 = __float2bfloat16(v.x - __bfloat162float(h0));
    bf16 l1 = __float2bfloat16(v.y - __bfloat162float(h1));
    bf16 l2 = __float2bfloat16(v.z - __bfloat162float(h2));
    bf16 l3 = __float2bfloat16(v.w - __bfloat162float(h3));
    ((__nv_bfloat162*)hi)[2*j]   = __nv_bfloat162(h0, h1);
    ((__nv_bfloat162*)hi)[2*j+1] = __nv_bfloat162(h2, h3);
    ((__nv_bfloat162*)lo)[2*j]   = __nv_bfloat162(l0, l1);
    ((__nv_bfloat162*)lo)[2*j+1] = __nv_bfloat162(l2, l3);
}

__global__ void split_kernel(const float* __restrict__ src,
                             bf16* __restrict__ hi, bf16* __restrict__ lo, int n4)
{
    int i = blockIdx.x * blockDim.x + threadIdx.x;
    if (i >= n4) return;
    split4_one(src, hi, lo, i);
}

// merged split for W_x, W_dt, W_out, W_head (one launch)
__global__ void split4_kernel(
    const float* __restrict__ s0, bf16* __restrict__ h0, bf16* __restrict__ l0, int n0,
    const float* __restrict__ s1, bf16* __restrict__ h1, bf16* __restrict__ l1, int n1,
    const float* __restrict__ s2, bf16* __restrict__ h2, bf16* __restrict__ l2, int n2,
    const float* __restrict__ s3, bf16* __restrict__ h3, bf16* __restrict__ l3, int n3)
{
    int i = blockIdx.x * blockDim.x + threadIdx.x;
    if (i < n0)                { split4_one(s0, h0, l0, i); return; }
    i -= n0;
    if (i < n1)                { split4_one(s1, h1, l1, i); return; }
    i -= n1;
    if (i < n2)                { split4_one(s2, h2, l2, i); return; }
    i -= n2;
    if (i < n3)                { split4_one(s3, h3, l3, i); return; }
}

// ---------------- dbl split-K reduce -> fp32 + hi/lo ----------------
__global__ void dbl_reduce_kernel(const float* __restrict__ part,
                                  float* __restrict__ dbl,
                                  bf16* __restrict__ dh, bf16* __restrict__ dl)
{
    int i = blockIdx.x * blockDim.x + threadIdx.x;
    if (i >= MROWS * DBLCOLS) return;
    float s = part[i];
    #pragma unroll
    for (int z = 1; z < KSPLIT; ++z) s += part[i + z * (MROWS * DBLCOLS)];
    dbl[i] = s;
    bf16 h = __float2bfloat16(s);
    dh[i] = h;
    dl[i] = __float2bfloat16(s - __bfloat162float(h));
}

// ---------------- embedding gather -> hi/lo ----------------
__global__ void embed_kernel(const int* __restrict__ ids,
                             const float* __restrict__ emb,
                             bf16* __restrict__ xhi, bf16* __restrict__ xlo)
{
    int idx = blockIdx.x * blockDim.x + threadIdx.x;
    if (idx >= MROWS * DIMM) return;
    int row = idx / DIMM, j = idx - row * DIMM;
    float v = emb[(size_t)ids[row] * DIMM + j];
    bf16 h = __float2bfloat16(v);
    xhi[idx] = h;
    xlo[idx] = __float2bfloat16(v - __bfloat162float(h));
}

// ---------------- depthwise causal conv (width 4) + SiLU ----------------
__global__ void conv_silu_kernel(const float* __restrict__ xz,
                                 const float* __restrict__ conv_w,
                                 const float* __restrict__ conv_b,
                                 float* __restrict__ xssm,
                                 bf16* __restrict__ xshi, bf16* __restrict__ xslo)
{
    int idx = blockIdx.x * blockDim.x + threadIdx.x;
    if (idx >= MROWS * DINNER) return;
    int d = idx % DINNER;
    int row = idx / DINNER;
    int b = row >> 11;
    int t = row & (SEQ - 1);
    float acc = conv_b[d];
    #pragma unroll
    for (int k = 0; k < DCONV; ++k) {
        int tt = t + k - (DCONV - 1);
        if (tt >= 0)
            acc = fmaf(xz[((size_t)(b * SEQ + tt)) * (2 * DINNER) + d],
                       conv_w[d * DCONV + k], acc);
    }
    float s = acc / (1.f + __expf(-acc));
    xssm[idx] = s;
    bf16 h = __float2bfloat16(s);
    xshi[idx] = h;
    xslo[idx] = __float2bfloat16(s - __bfloat162float(h));
}

// ---------------- chunked selective scan ----------------
__device__ __forceinline__ void load_coef(const float* __restrict__ A_log,
                                          int d, float coef[16], bool& pw)
{
    #pragma unroll
    for (int s = 0; s < 16; ++s)
        coef[s] = -__expf(A_log[d * 16 + s]) * LOG2E;
    pw = true;
    #pragma unroll
    for (int s = 1; s < 16; ++s) {
        float r = coef[s] / coef[0];
        pw = pw && (fabsf(r - (float)(s + 1)) < 1e-3f);
    }
}

__global__ __launch_bounds__(256) void scan_phase1(
    const float* __restrict__ dtb, const float* __restrict__ xs,
    const float* __restrict__ dbl, const float* __restrict__ A_log,
    float* __restrict__ hend, float* __restrict__ pend)
{
    int id = blockIdx.x * 256 + threadIdx.x;
    int ch = id % NCH, c = id / NCH;
    int b = ch / DINNER, d = ch - b * DINNER;

    float coef[16]; bool pw;
    load_coef(A_log, d, coef, pw);

    float h[16], P[16];
    #pragma unroll
    for (int s = 0; s < 16; ++s) { h[s] = 0.f; P[s] = 1.f; }

    int t0 = c * LCHUNK;
    for (int t = t0; t < t0 + LCHUNK; ++t) {
        int row = b * SEQ + t;
        size_t rb = (size_t)row * DINNER + d;
        float dt = __ldg(dtb + rb), xv = __ldg(xs + rb);
        float w = dt * xv;
        const float4* Bp = (const float4*)(dbl + (size_t)row * DBLCOLS + DTRANK);
        float4 B0 = __ldg(Bp), B1 = __ldg(Bp + 1), B2 = __ldg(Bp + 2), B3 = __ldg(Bp + 3);
        float Bv[16] = {B0.x,B0.y,B0.z,B0.w, B1.x,B1.y,B1.z,B1.w,
                        B2.x,B2.y,B2.z,B2.w, B3.x,B3.y,B3.z,B3.w};
        if (pw) {
            float E = exp2f(dt * coef[0]);
            float dA = 1.f;
            #pragma unroll
            for (int s = 0; s < 16; ++s) {
                dA *= E;
                h[s] = fmaf(h[s], dA, w * Bv[s]);
                P[s] *= dA;
            }
        } else {
            #pragma unroll
            for (int s = 0; s < 16; ++s) {
                float dA = exp2f(dt * coef[s]);
                h[s] = fmaf(h[s], dA, w * Bv[s]);
                P[s] *= dA;
            }
        }
    }
    size_t off = ((size_t)c * NCH + ch) * 16;
    float4* hp = (float4*)(hend + off);
    float4* pp = (float4*)(pend + off);
    #pragma unroll
    for (int q = 0; q < 4; ++q) {
        hp[q] = make_float4(h[4*q], h[4*q+1], h[4*q+2], h[4*q+3]);
        pp[q] = make_float4(P[4*q], P[4*q+1], P[4*q+2], P[4*q+3]);
    }
}

__global__ __launch_bounds__(256) void scan_phase2(
    const float* __restrict__ hend, const float* __restrict__ pend,
    float* __restrict__ hentry)
{
    int ch = blockIdx.x * 256 + threadIdx.x;
    float he[16];
    #pragma unroll
    for (int s = 0; s < 16; ++s) he[s] = 0.f;
    for (int c = 0; c < NCHUNK; ++c) {
        size_t off = ((size_t)c * NCH + ch) * 16;
        #pragma unroll
        for (int s = 0; s < 16; ++s) hentry[off + s] = he[s];
        #pragma unroll
        for (int s = 0; s < 16; ++s)
            he[s] = fmaf(pend[off + s], he[s], hend[off + s]);
    }
}

__global__ __launch_bounds__(256) void scan_phase3(
    const float* __restrict__ dtb, const float* __restrict__ xs,
    const float* __restrict__ dbl, const float* __restrict__ A_log,
    const float* __restrict__ hentry, const float* __restrict__ Dp,
    const float* __restrict__ xz,
    bf16* __restrict__ yhi, bf16* __restrict__ ylo)
{
    int id = blockIdx.x * 256 + threadIdx.x;
    int ch = id % NCH, c = id / NCH;
    int b = ch / DINNER, d = ch - b * DINNER;

    float coef[16]; bool pw;
    load_coef(A_log, d, coef, pw);
    float Dpd = __ldg(Dp + d);

    float h[16];
    {
        size_t off = ((size_t)c * NCH + ch) * 16;
        const float4* hp = (const float4*)(hentry + off);
        #pragma unroll
        for (int q = 0; q < 4; ++q) {
            float4 v = hp[q];
            h[4*q] = v.x; h[4*q+1] = v.y; h[4*q+2] = v.z; h[4*q+3] = v.w;
        }
    }

    int t0 = c * LCHUNK;
    for (int t = t0; t < t0 + LCHUNK; ++t) {
        int row = b * SEQ + t;
        size_t rb = (size_t)row * DINNER + d;
        float dt = __ldg(dtb + rb), xv = __ldg(xs + rb);
        float w = dt * xv;
        const float4* Bp = (const float4*)(dbl + (size_t)row * DBLCOLS + DTRANK);
        const float4* Cp = (const float4*)(dbl + (size_t)row * DBLCOLS + DTRANK + DSTATE);
        float4 B0 = __ldg(Bp), B1 = __ldg(Bp + 1), B2 = __ldg(Bp + 2), B3 = __ldg(Bp + 3);
        float4 C0 = __ldg(Cp), C1 = __ldg(Cp + 1), C2 = __ldg(Cp + 2), C3 = __ldg(Cp + 3);
        float Bv[16] = {B0.x,B0.y,B0.z,B0.w, B1.x,B1.y,B1.z,B1.w,
                        B2.x,B2.y,B2.z,B2.w, B3.x,B3.y,B3.z,B3.w};
        float Cv[16] = {C0.x,C0.y,C0.z,C0.w, C1.x,C1.y,C1.z,C1.w,
                        C2.x,C2.y,C2.z,C2.w, C3.x,C3.y,C3.z,C3.w};
        float y = 0.f;
        if (pw) {
            float E = exp2f(dt * coef[0]);
            float dA = 1.f;
            #pragma unroll
            for (int s = 0; s < 16; ++s) {
                dA *= E;
                h[s] = fmaf(h[s], dA, w * Bv[s]);
                y = fmaf(h[s], Cv[s], y);
            }
        } else {
            #pragma unroll
            for (int s = 0; s < 16; ++s) {
                float dA = exp2f(dt * coef[s]);
                h[s] = fmaf(h[s], dA, w * Bv[s]);
                y = fmaf(h[s], Cv[s], y);
            }
        }
        float z = __ldg(xz + (size_t)row * (2 * DINNER) + DINNER + d);
        float yy = fmaf(xv, Dpd, y);
        float sz = z / (1.f + __expf(-z));
        float out = yy * sz;
        bf16 hh = __float2bfloat16(out);
        yhi[rb] = hh;
        ylo[rb] = __float2bfloat16(out - __bfloat162float(hh));
    }
}

// ---------------- layernorm -> hi/lo ----------------
__global__ __launch_bounds__(256) void layernorm_kernel(
    const float* __restrict__ x, const float* __restrict__ g,
    const float* __restrict__ bb,
    bf16* __restrict__ ohi, bf16* __restrict__ olo)
{
    int row = blockIdx.x;
    const float* xr = x + (size_t)row * DIMM;
    float s = 0.f, s2 = 0.f;
    for (int j = threadIdx.x; j < DIMM; j += 256) {
        float v = xr[j];
        s += v; s2 = fmaf(v, v, s2);
    }
    #pragma unroll
    for (int o = 16; o > 0; o >>= 1) {
        s  += __shfl_xor_sync(0xffffffffu, s,  o);
        s2 += __shfl_xor_sync(0xffffffffu, s2, o);
    }
    __shared__ float rs[8], rs2[8];
    int w = threadIdx.x >> 5, l = threadIdx.x & 31;
    if (l == 0) { rs[w] = s; rs2[w] = s2; }
    __syncthreads();
    if (w == 0) {
        s  = (l < 8) ? rs[l]  : 0.f;
        s2 = (l < 8) ? rs2[l] : 0.f;
        #pragma unroll
        for (int o = 4; o > 0; o >>= 1) {
            s  += __shfl_xor_sync(0xffffffffu, s,  o);
            s2 += __shfl_xor_sync(0xffffffffu, s2, o);
        }
        if (l == 0) { rs[0] = s; rs2[0] = s2; }
    }
    __syncthreads();
    float mu = rs[0] * (1.f / DIMM);
    float var = rs2[0] * (1.f / DIMM) - mu * mu;
    float rstd = rsqrtf(var + 1e-5f);
    for (int j = threadIdx.x; j < DIMM; j += 256) {
        float v = (xr[j] - mu) * rstd * g[j] + bb[j];
        bf16 h = __float2bfloat16(v);
        ohi[(size_t)row * DIMM + j] = h;
        olo[(size_t)row * DIMM + j] = __float2bfloat16(v - __bfloat162float(h));
    }
}

// ---------------- host launcher ----------------
static inline void set_smem(const void* f, int bytes) {
    cudaFuncSetAttribute(f, cudaFuncAttributeMaxDynamicSharedMemorySize, bytes);
}

extern "C" void kernel_launch(void* const* d_in, const int* in_sizes, int n_in,
                              void* d_out, int out_size)
{
    const int*   ids    = (const int*)  d_in[0];
    const float* emb    = (const float*)d_in[1];
    const float* W_in   = (const float*)d_in[2];
    const float* conv_w = (const float*)d_in[3];
    const float* conv_b = (const float*)d_in[4];
    const float* W_x    = (const float*)d_in[5];
    const float* W_dt   = (const float*)d_in[6];
    const float* b_dt   = (const float*)d_in[7];
    const float* A_log  = (const float*)d_in[8];
    const float* Dp     = (const float*)d_in[9];
    const float* W_out  = (const float*)d_in[10];
    const float* ln_g   = (const float*)d_in[11];
    const float* ln_b   = (const float*)d_in[12];
    const float* W_head = (const float*)d_in[13];
    float* logits = (float*)d_out;

    float *x, *xz, *xssm, *dbl, *dblp, *dt, *he, *pe, *hh;
    cudaGetSymbolAddress((void**)&x,    g_x);
    cudaGetSymbolAddress((void**)&xz,   g_xz);
    cudaGetSymbolAddress((void**)&xssm, g_xssm);
    cudaGetSymbolAddress((void**)&dbl,  g_dbl);
    cudaGetSymbolAddress((void**)&dblp, g_dblp);
    cudaGetSymbolAddress((void**)&dt,   g_dt);
    cudaGetSymbolAddress((void**)&he,   g_hend);
    cudaGetSymbolAddress((void**)&pe,   g_pend);
    cudaGetSymbolAddress((void**)&hh,   g_hentry);

    bf16 *xhi,*xlo,*xshi,*xslo,*dblhi,*dbllo,*yhi,*ylo,*xlnhi,*xlnlo;
    bf16 *winhi,*winlo,*wxhi,*wxlo,*wdthi,*wdtlo,*wouthi,*woutlo,*wheadhi,*wheadlo;
    cudaGetSymbolAddress((void**)&xhi,    g_xhi);    cudaGetSymbolAddress((void**)&xlo,    g_xlo);
    cudaGetSymbolAddress((void**)&xshi,   g_xssmhi); cudaGetSymbolAddress((void**)&xslo,   g_xssmlo);
    cudaGetSymbolAddress((void**)&dblhi,  g_dblhi);  cudaGetSymbolAddress((void**)&dbllo,  g_dbllo);
    cudaGetSymbolAddress((void**)&yhi,    g_yhi);    cudaGetSymbolAddress((void**)&ylo,    g_ylo);
    cudaGetSymbolAddress((void**)&xlnhi,  g_xlnhi);  cudaGetSymbolAddress((void**)&xlnlo,  g_xlnlo);
    cudaGetSymbolAddress((void**)&winhi,  g_winhi);  cudaGetSymbolAddress((void**)&winlo,  g_winlo);
    cudaGetSymbolAddress((void**)&wxhi,   g_wxhi);   cudaGetSymbolAddress((void**)&wxlo,   g_wxlo);
    cudaGetSymbolAddress((void**)&wdthi,  g_wdthi);  cudaGetSymbolAddress((void**)&wdtlo,  g_wdtlo);
    cudaGetSymbolAddress((void**)&wouthi, g_wouthi); cudaGetSymbolAddress((void**)&woutlo, g_woutlo);
    cudaGetSymbolAddress((void**)&wheadhi,g_wheadhi);cudaGetSymbolAddress((void**)&wheadlo,g_wheadlo);

    set_smem((const void*)mma_gemm<0>, SMB);
    set_smem((const void*)mma_gemm<1>, SMB);
    set_smem((const void*)mma_gemm<2>, SMB);

    // ---- launch order: ncu (-s 5 -c 1) captures kernel_launch index 3 ----
    // [0] embed  [1] W_in split  [2] merged split4  [3] xz GEMM (profiled)
    embed_kernel<<<(MROWS * DIMM + 255) / 256, 256>>>(ids, emb, xhi, xlo);

    {
        int n = 4 * 2 * DINNER * DIMM;
        split_kernel<<<(n/4+255)/256,256>>>(W_in, winhi, winlo, n/4);
        int n0 = (4 * DBLCOLS * DINNER) / 4;
        int n1 = (4 * DINNER * DTRANK) / 4;
        int n2 = (4 * DIMM * DINNER) / 4;
        int n3 = (VOCAB * DIMM) / 4;
        split4_kernel<<<(n0+n1+n2+n3+255)/256,256>>>(
            W_x,   wxhi,   wxlo,   n0,
            W_dt,  wdthi,  wdtlo,  n1,
            W_out, wouthi, woutlo, n2,
            W_head,wheadhi,wheadlo,n3);
    }

    for (int i = 0; i < 4; ++i) {
        // xz = x @ W_in^T : [4096, 3072], K=768
        mma_gemm<0><<<dim3((2*DINNER)/96, MROWS/128), 256, SMB>>>(
            MROWS, 2*DINNER, DIMM,
            xhi, xlo, DIMM,
            winhi + (size_t)i * 2*DINNER*DIMM, winlo + (size_t)i * 2*DINNER*DIMM, DIMM,
            nullptr, xz, 2*DINNER, nullptr, nullptr);

        conv_silu_kernel<<<(MROWS * DINNER + 255) / 256, 256>>>(
            xz, conv_w + (size_t)i * DINNER * DCONV, conv_b + (size_t)i * DINNER,
            xssm, xshi, xslo);

        // dbl partials: x_ssm @ W_x^T split-K (K = 1536 -> 4 x 384)
        mma_gemm<0><<<dim3(1, MROWS/128, KSPLIT), 256, SMB>>>(
            MROWS, DBLCOLS, DINNER / KSPLIT,
            xshi, xslo, DINNER,
            wxhi + (size_t)i * DBLCOLS * DINNER, wxlo + (size_t)i * DBLCOLS * DINNER, DINNER,
            nullptr, dblp, DBLCOLS, nullptr, nullptr);
        dbl_reduce_kernel<<<(MROWS * DBLCOLS + 255) / 256, 256>>>(dblp, dbl, dblhi, dbllo);

        // dt = softplus(dbl[:, :48] @ W_dt^T + b_dt) : [4096, 1536], K=48
        mma_gemm<1><<<dim3(DINNER/96, MROWS/128), 256, SMB>>>(
            MROWS, DINNER, DTRANK,
            dblhi, dbllo, DBLCOLS,
            wdthi + (size_t)i * DINNER * DTRANK, wdtlo + (size_t)i * DINNER * DTRANK, DTRANK,
            b_dt + (size_t)i * DINNER, dt, DINNER, nullptr, nullptr);

        const float* Al = A_log + (size_t)i * DINNER * DSTATE;
        scan_phase1<<<(NCHUNK * NCH) / 256, 256>>>(dt, xssm, dbl, Al, he, pe);
        scan_phase2<<<NCH / 256, 256>>>(he, pe, hh);
        scan_phase3<<<(NCHUNK * NCH) / 256, 256>>>(dt, xssm, dbl, Al, hh,
                                                   Dp + (size_t)i * DINNER, xz, yhi, ylo);

        // x = y @ W_out^T : [4096, 768], K=1536
        mma_gemm<2><<<dim3(DIMM/96, MROWS/128), 256, SMB>>>(
            MROWS, DIMM, DINNER,
            yhi, ylo, DINNER,
            wouthi + (size_t)i * DIMM * DINNER, woutlo + (size_t)i * DIMM * DINNER, DINNER,
            nullptr, x, DIMM, xhi, xlo);
    }

    layernorm_kernel<<<MROWS, 256>>>(x, ln_g, ln_b, xlnhi, xlnlo);

    // logits = x_ln @ W_head^T : [4096, 32000], K=768
    mma_gemm<0><<<dim3((VOCAB + 95)/96, MROWS/128), 256, SMB>>>(
        MROWS, VOCAB, DIMM,
        xlnhi, xlnlo, DIMM,
        wheadhi, wheadlo, DIMM,
        nullptr, logits, VOCAB, nullptr, nullptr);
}

// round 15
// speedup vs baseline: 1.0541x; 1.0541x over previous
#include <cuda_runtime.h>
#include <cuda_bf16.h>
#include <cstdint>

// ---------------- problem constants ----------------
#define NB      2
#define SEQ     2048
#define DIMM    768
#define DINNER  1536
#define DSTATE  16
#define DCONV   4
#define DTRANK  48
#define MROWS   (NB*SEQ)            // 4096
#define DBLCOLS 80
#define VOCAB   32000
#define NCHUNK  32
#define LCHUNK  (SEQ/NCHUNK)        // 64
#define NCH     (NB*DINNER)         // 3072
#define LOG2E   1.4426950408889634f
#define KSPLIT  4

typedef __nv_bfloat16 bf16;

// ---------------- fp32 scratch ----------------
__device__ float g_x   [MROWS * DIMM];
__device__ float g_xz  [MROWS * 2 * DINNER];
__device__ float g_xssm[MROWS * DINNER];
__device__ float g_dbl [MROWS * DBLCOLS];
__device__ float g_dblp[KSPLIT * MROWS * DBLCOLS];
__device__ float g_dt  [MROWS * DINNER];
__device__ float g_hend  [NCHUNK * NCH * DSTATE];
__device__ float g_pend  [NCHUNK * NCH * DSTATE];
__device__ float g_hentry[NCHUNK * NCH * DSTATE];

// ---------------- bf16 hi/lo scratch ----------------
__device__ __align__(16) bf16 g_xhi   [MROWS * DIMM],   g_xlo   [MROWS * DIMM];
__device__ __align__(16) bf16 g_xssmhi[MROWS * DINNER], g_xssmlo[MROWS * DINNER];
__device__ __align__(16) bf16 g_dblhi [MROWS * DBLCOLS],g_dbllo [MROWS * DBLCOLS];
__device__ __align__(16) bf16 g_yhi   [MROWS * DINNER], g_ylo   [MROWS * DINNER];
__device__ __align__(16) bf16 g_xlnhi [MROWS * DIMM],   g_xlnlo [MROWS * DIMM];
__device__ __align__(16) bf16 g_winhi [4 * 2 * DINNER * DIMM],  g_winlo [4 * 2 * DINNER * DIMM];
__device__ __align__(16) bf16 g_wxhi  [4 * DBLCOLS * DINNER],   g_wxlo  [4 * DBLCOLS * DINNER];
__device__ __align__(16) bf16 g_wdthi [4 * DINNER * DTRANK],    g_wdtlo [4 * DINNER * DTRANK];
__device__ __align__(16) bf16 g_wouthi[4 * DIMM * DINNER],      g_woutlo[4 * DIMM * DINNER];
__device__ __align__(16) bf16 g_wheadhi[VOCAB * DIMM],          g_wheadlo[VOCAB * DIMM];

// =====================================================================
// low-level helpers
// =====================================================================
__device__ __forceinline__ void cp_async16(uint32_t dst, const void* src, bool pred) {
    int sz = pred ? 16 : 0;
    asm volatile("cp.async.cg.shared.global [%0], [%1], 16, %2;\n"
                 :: "r"(dst), "l"(src), "r"(sz));
}
__device__ __forceinline__ void cp_commit() {
    asm volatile("cp.async.commit_group;\n" ::: "memory");
}
template<int N>
__device__ __forceinline__ void cp_wait() {
    asm volatile("cp.async.wait_group %0;\n" :: "n"(N) : "memory");
}

__device__ __forceinline__ void ldsm_x4(uint32_t* r, uint32_t addr) {
    asm volatile("ldmatrix.sync.aligned.m8n8.x4.shared.b16 {%0,%1,%2,%3}, [%4];"
                 : "=r"(r[0]), "=r"(r[1]), "=r"(r[2]), "=r"(r[3]) : "r"(addr));
}

__device__ __forceinline__ void mma_bf16(float c[4], const uint32_t a[4],
                                         uint32_t b0, uint32_t b1) {
    asm volatile(
        "mma.sync.aligned.m16n8k16.row.col.f32.bf16.bf16.f32 "
        "{%0,%1,%2,%3}, {%4,%5,%6,%7}, {%8,%9}, {%0,%1,%2,%3};\n"
        : "+f"(c[0]), "+f"(c[1]), "+f"(c[2]), "+f"(c[3])
        : "r"(a[0]), "r"(a[1]), "r"(a[2]), "r"(a[3]), "r"(b0), "r"(b1));
}

// =====================================================================
// bf16 hi/lo mma GEMM:  C = (Ahi+Alo) * (Bhi+Blo)^T
// THIS ROUND: warp tile 64x48 (4 warps, 128 threads, 2m x 2n) to raise
// MACs per smem-crossbar byte 1.4x (crossbar+tensor co-bound model).
// CTA tile 128x96, 3-stage cp.async pipeline, ONE barrier per K-tile,
// mma.m16n8k16, ldmatrix, 80B-padded rows (conflict-free). occ 2.
// acc 96 regs/thread; 128-thr CTA -> 256-reg budget, no cap.
// Optional split-K via blockIdx.z.
// EPI 0: C fp32.  EPI 1: softplus(acc + bias[n]).  EPI 2: fp32 + hi/lo split.
// =====================================================================
#define GBK    32
#define ROWB   80          // padded row bytes (conflict-free for ldmatrix)
#define BUFA   10240       // 128 rows * 80
#define BUFB2  7680        // 96 rows * 80
#define SSB    35840       // stage bytes: Ahi,Alo,Bhi,Blo
#define NSTAGE 3
#define SMB    (NSTAGE*SSB)   // 107520
#define NCHUNKS 1792          // (128+128+96+96)*4 16B-chunks per stage

template<int EPI>
__global__ void __launch_bounds__(128, 2) mma_gemm(
    int M, int N, int K,
    const bf16* __restrict__ Ahi, const bf16* __restrict__ Alo, int lda,
    const bf16* __restrict__ Bhi, const bf16* __restrict__ Blo, int ldb,
    const float* __restrict__ bias,
    float* __restrict__ C, int ldc,
    bf16* __restrict__ Chi, bf16* __restrict__ Clo)
{
    extern __shared__ char smem[];
    const uint32_t sb = (uint32_t)__cvta_generic_to_shared(smem);

    const int tid  = threadIdx.x;
    const int lane = tid & 31;
    const int warp = tid >> 5;          // 0..3
    const int wm   = (warp >> 1) * 64;  // warp M offset 0/64
    const int wn   = (warp & 1) * 48;   // warp N offset 0/48

    const int bm = blockIdx.y * 128;
    const int bn = blockIdx.x * 96;

    const int koff = blockIdx.z * K;
    Ahi += koff; Alo += koff; Bhi += koff; Blo += koff;
    C += (size_t)blockIdx.z * (size_t)M * (size_t)ldc;

    const int la_row = (lane & 7) + ((lane >> 3) & 1) * 8;
    const int la_col = (lane >> 4) * 8;
    const int lb_row = (lane & 7) + (lane >> 4) * 8;
    const int lb_col = ((lane >> 3) & 1) * 8;

    const uint32_t aoff = (uint32_t)(wm + la_row) * ROWB + la_col * 2;
    const uint32_t boff = (uint32_t)(wn + lb_row) * ROWB + lb_col * 2;

    float acc[4][6][4];
    #pragma unroll
    for (int i = 0; i < 4; ++i)
        #pragma unroll
        for (int j = 0; j < 6; ++j)
            #pragma unroll
            for (int q = 0; q < 4; ++q) acc[i][j][q] = 0.f;

    const int ntiles = (K + GBK - 1) / GBK;

    auto fill = [&](int s, int kc) {
        const uint32_t base = sb + (uint32_t)s * SSB;
        const int k0 = kc * GBK;
        #pragma unroll
        for (int i = 0; i < 14; ++i) {      // 14 * 128 = 1792 = NCHUNKS
            int c = tid + i * 128;
            if (c < 1024) {                 // A: 2 x 512 chunks
                int buf = c >> 9;
                int cc = c & 511;
                int row = cc >> 2, q = cc & 3;
                uint32_t dst = base + (uint32_t)buf * BUFA
                             + (uint32_t)row * ROWB + q * 16;
                bool kok = (k0 + q * 8) < K;
                const bf16* src = buf ? Alo : Ahi;
                cp_async16(dst, src + (size_t)(bm + row) * lda + k0 + q * 8, kok);
            } else {                        // B: 2 x 384 chunks
                int d = c - 1024;
                int buf = d >= 384;
                int cc = d - (buf ? 384 : 0);
                int row = cc >> 2, q = cc & 3;
                uint32_t dst = base + 2 * BUFA + (uint32_t)buf * BUFB2
                             + (uint32_t)row * ROWB + q * 16;
                bool rp = (bn + row) < N;
                bool kok = (k0 + q * 8) < K;
                int r = rp ? (bn + row) : 0;
                const bf16* src = buf ? Blo : Bhi;
                cp_async16(dst, src + (size_t)r * ldb + k0 + q * 8, kok && rp);
            }
        }
    };

    // prologue: 2 stages in flight
    fill(0, 0);
    cp_commit();
    if (ntiles > 1) fill(1, 1);
    cp_commit();

    for (int t = 0; t < ntiles; ++t) {
        const int s = t % NSTAGE;
        cp_wait<1>();             // fill(t) complete
        __syncthreads();          // single barrier per tile
        if (t + 2 < ntiles) fill((t + 2) % NSTAGE, t + 2);
        cp_commit();

        const uint32_t base = sb + (uint32_t)s * SSB;
        #pragma unroll
        for (int ks = 0; ks < 2; ++ks) {
            const uint32_t kb = ks * 32;
            uint32_t ah[4][4], al[4][4], bh[3][4], bl[3][4];
            #pragma unroll
            for (int mt = 0; mt < 4; ++mt) {
                uint32_t a = base + aoff + (uint32_t)mt * (16 * ROWB) + kb;
                ldsm_x4(ah[mt], a);
                ldsm_x4(al[mt], a + BUFA);
            }
            #pragma unroll
            for (int pt = 0; pt < 3; ++pt) {
                uint32_t b = base + 2 * BUFA + boff + (uint32_t)pt * (16 * ROWB) + kb;
                ldsm_x4(bh[pt], b);
                ldsm_x4(bl[pt], b + BUFB2);
            }
            // term 1: hi*hi
            #pragma unroll
            for (int mt = 0; mt < 4; ++mt)
                #pragma unroll
                for (int nt = 0; nt < 6; ++nt) {
                    const int pt = nt >> 1, j = (nt & 1) * 2;
                    mma_bf16(acc[mt][nt], ah[mt], bh[pt][j], bh[pt][j + 1]);
                }
            // term 2: hi*lo
            #pragma unroll
            for (int mt = 0; mt < 4; ++mt)
                #pragma unroll
                for (int nt = 0; nt < 6; ++nt) {
                    const int pt = nt >> 1, j = (nt & 1) * 2;
                    mma_bf16(acc[mt][nt], ah[mt], bl[pt][j], bl[pt][j + 1]);
                }
            // term 3: lo*hi
            #pragma unroll
            for (int mt = 0; mt < 4; ++mt)
                #pragma unroll
                for (int nt = 0; nt < 6; ++nt) {
                    const int pt = nt >> 1, j = (nt & 1) * 2;
                    mma_bf16(acc[mt][nt], al[mt], bh[pt][j], bh[pt][j + 1]);
                }
        }
    }

    __syncthreads();

    // ---- epilogue ----
    #pragma unroll
    for (int mt = 0; mt < 4; ++mt) {
        const int row0 = bm + wm + mt * 16 + (lane >> 2);
        const int row1 = row0 + 8;
        #pragma unroll
        for (int nt = 0; nt < 6; ++nt) {
            const int col = bn + wn + nt * 8 + 2 * (lane & 3);
            if (col >= N) continue;
            float v0 = acc[mt][nt][0], v1 = acc[mt][nt][1];
            float v2 = acc[mt][nt][2], v3 = acc[mt][nt][3];
            if (EPI == 1) {
                float b0 = bias[col], b1 = bias[col + 1];
                v0 += b0; v1 += b1; v2 += b0; v3 += b1;
                v0 = fmaxf(v0, 0.f) + log1pf(__expf(-fabsf(v0)));
                v1 = fmaxf(v1, 0.f) + log1pf(__expf(-fabsf(v1)));
                v2 = fmaxf(v2, 0.f) + log1pf(__expf(-fabsf(v2)));
                v3 = fmaxf(v3, 0.f) + log1pf(__expf(-fabsf(v3)));
            }
            *(float2*)(C + (size_t)row0 * ldc + col) = make_float2(v0, v1);
            *(float2*)(C + (size_t)row1 * ldc + col) = make_float2(v2, v3);
            if (EPI == 2) {
                bf16 h0 = __float2bfloat16(v0), h1 = __float2bfloat16(v1);
                bf16 h2 = __float2bfloat16(v2), h3 = __float2bfloat16(v3);
                bf16 l0 = __float2bfloat16(v0 - __bfloat162float(h0));
                bf16 l1 = __float2bfloat16(v1 - __bfloat162float(h1));
                bf16 l2 = __float2bfloat16(v2 - __bfloat162float(h2));
                bf16 l3 = __float2bfloat16(v3 - __bfloat162float(h3));
                *(__nv_bfloat162*)(Chi + (size_t)row0 * ldc + col) = __nv_bfloat162(h0, h1);
                *(__nv_bfloat162*)(Chi + (size_t)row1 * ldc + col) = __nv_bfloat162(h2, h3);
                *(__nv_bfloat162*)(Clo + (size_t)row0 * ldc + col) = __nv_bfloat162(l0, l1);
                *(__nv_bfloat162*)(Clo + (size_t)row1 * ldc + col) = __nv_bfloat162(l2, l3);
            }
        }
    }
}

// ---------------- weight fp32 -> bf16 hi/lo split ----------------
__device__ __forceinline__ void split4_one(const float* __restrict__ src,
                                           bf16* __restrict__ hi,
                                           bf16* __restrict__ lo, int j)
{
    float4 v = ((const float4*)src)[j];
    bf16 h0 = __float2bfloat16(v.x), h1 = __float2bfloat16(v.y);
    bf16 h2 = __float2bfloat16(v.z), h3 = __float2bfloat16(v.w);
    bf16 l0 = __float2bfloat16(v.x - __bfloat162float(h0));
    bf16 l1 = __float2bfloat16(v.y - __bfloat162float(h1));
    bf16 l2 = __float2bfloat16(v.z - __bfloat162float(h2));
    bf16 l3 = __float2bfloat16(v.w - __bfloat162float(h3));
    ((__nv_bfloat162*)hi)[2*j]   = __nv_bfloat162(h0, h1);
    ((__nv_bfloat162*)hi)[2*j+1] = __nv_bfloat162(h2, h3);
    ((__nv_bfloat162*)lo)[2*j]   = __nv_bfloat162(l0, l1);
    ((__nv_bfloat162*)lo)[2*j+1] = __nv_bfloat162(l2, l3);
}

__global__ void split_kernel(const float* __restrict__ src,
                             bf16* __restrict__ hi, bf16* __restrict__ lo, int n4)
{
    int i = blockIdx.x * blockDim.x + threadIdx.x;
    if (i >= n4) return;
    split4_one(src, hi, lo, i);
}

// merged split for W_x, W_dt, W_out, W_head (one launch)
__global__ void split4_kernel(
    const float* __restrict__ s0, bf16* __restrict__ h0, bf16* __restrict__ l0, int n0,
    const float* __restrict__ s1, bf16* __restrict__ h1, bf16* __restrict__ l1, int n1,
    const float* __restrict__ s2, bf16* __restrict__ h2, bf16* __restrict__ l2, int n2,
    const float* __restrict__ s3, bf16* __restrict__ h3, bf16* __restrict__ l3, int n3)
{
    int i = blockIdx.x * blockDim.x + threadIdx.x;
    if (i < n0)                { split4_one(s0, h0, l0, i); return; }
    i -= n0;
    if (i < n1)                { split4_one(s1, h1, l1, i); return; }
    i -= n1;
    if (i < n2)                { split4_one(s2, h2, l2, i); return; }
    i -= n2;
    if (i < n3)                { split4_one(s3, h3, l3, i); return; }
}

// ---------------- dbl split-K reduce -> fp32 + hi/lo ----------------
__global__ void dbl_reduce_kernel(const float* __restrict__ part,
                                  float* __restrict__ dbl,
                                  bf16* __restrict__ dh, bf16* __restrict__ dl)
{
    int i = blockIdx.x * blockDim.x + threadIdx.x;
    if (i >= MROWS * DBLCOLS) return;
    float s = part[i];
    #pragma unroll
    for (int z = 1; z < KSPLIT; ++z) s += part[i + z * (MROWS * DBLCOLS)];
    dbl[i] = s;
    bf16 h = __float2bfloat16(s);
    dh[i] = h;
    dl[i] = __float2bfloat16(s - __bfloat162float(h));
}

// ---------------- embedding gather -> hi/lo ----------------
__global__ void embed_kernel(const int* __restrict__ ids,
                             const float* __restrict__ emb,
                             bf16* __restrict__ xhi, bf16* __restrict__ xlo)
{
    int idx = blockIdx.x * blockDim.x + threadIdx.x;
    if (idx >= MROWS * DIMM) return;
    int row = idx / DIMM, j = idx - row * DIMM;
    float v = emb[(size_t)ids[row] * DIMM + j];
    bf16 h = __float2bfloat16(v);
    xhi[idx] = h;
    xlo[idx] = __float2bfloat16(v - __bfloat162float(h));
}

// ---------------- depthwise causal conv (width 4) + SiLU ----------------
__global__ void conv_silu_kernel(const float* __restrict__ xz,
                                 const float* __restrict__ conv_w,
                                 const float* __restrict__ conv_b,
                                 float* __restrict__ xssm,
                                 bf16* __restrict__ xshi, bf16* __restrict__ xslo)
{
    int idx = blockIdx.x * blockDim.x + threadIdx.x;
    if (idx >= MROWS * DINNER) return;
    int d = idx % DINNER;
    int row = idx / DINNER;
    int b = row >> 11;
    int t = row & (SEQ - 1);
    float acc = conv_b[d];
    #pragma unroll
    for (int k = 0; k < DCONV; ++k) {
        int tt = t + k - (DCONV - 1);
        if (tt >= 0)
            acc = fmaf(xz[((size_t)(b * SEQ + tt)) * (2 * DINNER) + d],
                       conv_w[d * DCONV + k], acc);
    }
    float s = acc / (1.f + __expf(-acc));
    xssm[idx] = s;
    bf16 h = __float2bfloat16(s);
    xshi[idx] = h;
    xslo[idx] = __float2bfloat16(s - __bfloat162float(h));
}

// ---------------- chunked selective scan ----------------
__device__ __forceinline__ void load_coef(const float* __restrict__ A_log,
                                          int d, float coef[16], bool& pw)
{
    #pragma unroll
    for (int s = 0; s < 16; ++s)
        coef[s] = -__expf(A_log[d * 16 + s]) * LOG2E;
    pw = true;
    #pragma unroll
    for (int s = 1; s < 16; ++s) {
        float r = coef[s] / coef[0];
        pw = pw && (fabsf(r - (float)(s + 1)) < 1e-3f);
    }
}

__global__ __launch_bounds__(256) void scan_phase1(
    const float* __restrict__ dtb, const float* __restrict__ xs,
    const float* __restrict__ dbl, const float* __restrict__ A_log,
    float* __restrict__ hend, float* __restrict__ pend)
{
    int id = blockIdx.x * 256 + threadIdx.x;
    int ch = id % NCH, c = id / NCH;
    int b = ch / DINNER, d = ch - b * DINNER;

    float coef[16]; bool pw;
    load_coef(A_log, d, coef, pw);

    float h[16], P[16];
    #pragma unroll
    for (int s = 0; s < 16; ++s) { h[s] = 0.f; P[s] = 1.f; }

    int t0 = c * LCHUNK;
    for (int t = t0; t < t0 + LCHUNK; ++t) {
        int row = b * SEQ + t;
        size_t rb = (size_t)row * DINNER + d;
        float dt = __ldg(dtb + rb), xv = __ldg(xs + rb);
        float w = dt * xv;
        const float4* Bp = (const float4*)(dbl + (size_t)row * DBLCOLS + DTRANK);
        float4 B0 = __ldg(Bp), B1 = __ldg(Bp + 1), B2 = __ldg(Bp + 2), B3 = __ldg(Bp + 3);
        float Bv[16] = {B0.x,B0.y,B0.z,B0.w, B1.x,B1.y,B1.z,B1.w,
                        B2.x,B2.y,B2.z,B2.w, B3.x,B3.y,B3.z,B3.w};
        if (pw) {
            float E = exp2f(dt * coef[0]);
            float dA = 1.f;
            #pragma unroll
            for (int s = 0; s < 16; ++s) {
                dA *= E;
                h[s] = fmaf(h[s], dA, w * Bv[s]);
                P[s] *= dA;
            }
        } else {
            #pragma unroll
            for (int s = 0; s < 16; ++s) {
                float dA = exp2f(dt * coef[s]);
                h[s] = fmaf(h[s], dA, w * Bv[s]);
                P[s] *= dA;
            }
        }
    }
    size_t off = ((size_t)c * NCH + ch) * 16;
    float4* hp = (float4*)(hend + off);
    float4* pp = (float4*)(pend + off);
    #pragma unroll
    for (int q = 0; q < 4; ++q) {
        hp[q] = make_float4(h[4*q], h[4*q+1], h[4*q+2], h[4*q+3]);
        pp[q] = make_float4(P[4*q], P[4*q+1], P[4*q+2], P[4*q+3]);
    }
}

__global__ __launch_bounds__(256) void scan_phase2(
    const float* __restrict__ hend, const float* __restrict__ pend,
    float* __restrict__ hentry)
{
    int ch = blockIdx.x * 256 + threadIdx.x;
    float he[16];
    #pragma unroll
    for (int s = 0; s < 16; ++s) he[s] = 0.f;
    for (int c = 0; c < NCHUNK; ++c) {
        size_t off = ((size_t)c * NCH + ch) * 16;
        #pragma unroll
        for (int s = 0; s < 16; ++s) hentry[off + s] = he[s];
        #pragma unroll
        for (int s = 0; s < 16; ++s)
            he[s] = fmaf(pend[off + s], he[s], hend[off + s]);
    }
}

__global__ __launch_bounds__(256) void scan_phase3(
    const float* __restrict__ dtb, const float* __restrict__ xs,
    const float* __restrict__ dbl, const float* __restrict__ A_log,
    const float* __restrict__ hentry, const float* __restrict__ Dp,
    const float* __restrict__ xz,
    bf16* __restrict__ yhi, bf16* __restrict__ ylo)
{
    int id = blockIdx.x * 256 + threadIdx.x;
    int ch = id % NCH, c = id / NCH;
    int b = ch / DINNER, d = ch - b * DINNER;

    float coef[16]; bool pw;
    load_coef(A_log, d, coef, pw);
    float Dpd = __ldg(Dp + d);

    float h[16];
    {
        size_t off = ((size_t)c * NCH + ch) * 16;
        const float4* hp = (const float4*)(hentry + off);
        #pragma unroll
        for (int q = 0; q < 4; ++q) {
            float4 v = hp[q];
            h[4*q] = v.x; h[4*q+1] = v.y; h[4*q+2] = v.z; h[4*q+3] = v.w;
        }
    }

    int t0 = c * LCHUNK;
    for (int t = t0; t < t0 + LCHUNK; ++t) {
        int row = b * SEQ + t;
        size_t rb = (size_t)row * DINNER + d;
        float dt = __ldg(dtb + rb), xv = __ldg(xs + rb);
        float w = dt * xv;
        const float4* Bp = (const float4*)(dbl + (size_t)row * DBLCOLS + DTRANK);
        const float4* Cp = (const float4*)(dbl + (size_t)row * DBLCOLS + DTRANK + DSTATE);
        float4 B0 = __ldg(Bp), B1 = __ldg(Bp + 1), B2 = __ldg(Bp + 2), B3 = __ldg(Bp + 3);
        float4 C0 = __ldg(Cp), C1 = __ldg(Cp + 1), C2 = __ldg(Cp + 2), C3 = __ldg(Cp + 3);
        float Bv[16] = {B0.x,B0.y,B0.z,B0.w, B1.x,B1.y,B1.z,B1.w,
                        B2.x,B2.y,B2.z,B2.w, B3.x,B3.y,B3.z,B3.w};
        float Cv[16] = {C0.x,C0.y,C0.z,C0.w, C1.x,C1.y,C1.z,C1.w,
                        C2.x,C2.y,C2.z,C2.w, C3.x,C3.y,C3.z,C3.w};
        float y = 0.f;
        if (pw) {
            float E = exp2f(dt * coef[0]);
            float dA = 1.f;
            #pragma unroll
            for (int s = 0; s < 16; ++s) {
                dA *= E;
                h[s] = fmaf(h[s], dA, w * Bv[s]);
                y = fmaf(h[s], Cv[s], y);
            }
        } else {
            #pragma unroll
            for (int s = 0; s < 16; ++s) {
                float dA = exp2f(dt * coef[s]);
                h[s] = fmaf(h[s], dA, w * Bv[s]);
                y = fmaf(h[s], Cv[s], y);
            }
        }
        float z = __ldg(xz + (size_t)row * (2 * DINNER) + DINNER + d);
        float yy = fmaf(xv, Dpd, y);
        float sz = z / (1.f + __expf(-z));
        float out = yy * sz;
        bf16 hh = __float2bfloat16(out);
        yhi[rb] = hh;
        ylo[rb] = __float2bfloat16(out - __bfloat162float(hh));
    }
}

// ---------------- layernorm -> hi/lo ----------------
__global__ __launch_bounds__(256) void layernorm_kernel(
    const float* __restrict__ x, const float* __restrict__ g,
    const float* __restrict__ bb,
    bf16* __restrict__ ohi, bf16* __restrict__ olo)
{
    int row = blockIdx.x;
    const float* xr = x + (size_t)row * DIMM;
    float s = 0.f, s2 = 0.f;
    for (int j = threadIdx.x; j < DIMM; j += 256) {
        float v = xr[j];
        s += v; s2 = fmaf(v, v, s2);
    }
    #pragma unroll
    for (int o = 16; o > 0; o >>= 1) {
        s  += __shfl_xor_sync(0xffffffffu, s,  o);
        s2 += __shfl_xor_sync(0xffffffffu, s2, o);
    }
    __shared__ float rs[8], rs2[8];
    int w = threadIdx.x >> 5, l = threadIdx.x & 31;
    if (l == 0) { rs[w] = s; rs2[w] = s2; }
    __syncthreads();
    if (w == 0) {
        s  = (l < 8) ? rs[l]  : 0.f;
        s2 = (l < 8) ? rs2[l] : 0.f;
        #pragma unroll
        for (int o = 4; o > 0; o >>= 1) {
            s  += __shfl_xor_sync(0xffffffffu, s,  o);
            s2 += __shfl_xor_sync(0xffffffffu, s2, o);
        }
        if (l == 0) { rs[0] = s; rs2[0] = s2; }
    }
    __syncthreads();
    float mu = rs[0] * (1.f / DIMM);
    float var = rs2[0] * (1.f / DIMM) - mu * mu;
    float rstd = rsqrtf(var + 1e-5f);
    for (int j = threadIdx.x; j < DIMM; j += 256) {
        float v = (xr[j] - mu) * rstd * g[j] + bb[j];
        bf16 h = __float2bfloat16(v);
        ohi[(size_t)row * DIMM + j] = h;
        olo[(size_t)row * DIMM + j] = __float2bfloat16(v - __bfloat162float(h));
    }
}

// ---------------- host launcher ----------------
static inline void set_smem(const void* f, int bytes) {
    cudaFuncSetAttribute(f, cudaFuncAttributeMaxDynamicSharedMemorySize, bytes);
}

extern "C" void kernel_launch(void* const* d_in, const int* in_sizes, int n_in,
                              void* d_out, int out_size)
{
    const int*   ids    = (const int*)  d_in[0];
    const float* emb    = (const float*)d_in[1];
    const float* W_in   = (const float*)d_in[2];
    const float* conv_w = (const float*)d_in[3];
    const float* conv_b = (const float*)d_in[4];
    const float* W_x    = (const float*)d_in[5];
    const float* W_dt   = (const float*)d_in[6];
    const float* b_dt   = (const float*)d_in[7];
    const float* A_log  = (const float*)d_in[8];
    const float* Dp     = (const float*)d_in[9];
    const float* W_out  = (const float*)d_in[10];
    const float* ln_g   = (const float*)d_in[11];
    const float* ln_b   = (const float*)d_in[12];
    const float* W_head = (const float*)d_in[13];
    float* logits = (float*)d_out;

    float *x, *xz, *xssm, *dbl, *dblp, *dt, *he, *pe, *hh;
    cudaGetSymbolAddress((void**)&x,    g_x);
    cudaGetSymbolAddress((void**)&xz,   g_xz);
    cudaGetSymbolAddress((void**)&xssm, g_xssm);
    cudaGetSymbolAddress((void**)&dbl,  g_dbl);
    cudaGetSymbolAddress((void**)&dblp, g_dblp);
    cudaGetSymbolAddress((void**)&dt,   g_dt);
    cudaGetSymbolAddress((void**)&he,   g_hend);
    cudaGetSymbolAddress((void**)&pe,   g_pend);
    cudaGetSymbolAddress((void**)&hh,   g_hentry);

    bf16 *xhi,*xlo,*xshi,*xslo,*dblhi,*dbllo,*yhi,*ylo,*xlnhi,*xlnlo;
    bf16 *winhi,*winlo,*wxhi,*wxlo,*wdthi,*wdtlo,*wouthi,*woutlo,*wheadhi,*wheadlo;
    cudaGetSymbolAddress((void**)&xhi,    g_xhi);    cudaGetSymbolAddress((void**)&xlo,    g_xlo);
    cudaGetSymbolAddress((void**)&xshi,   g_xssmhi); cudaGetSymbolAddress((void**)&xslo,   g_xssmlo);
    cudaGetSymbolAddress((void**)&dblhi,  g_dblhi);  cudaGetSymbolAddress((void**)&dbllo,  g_dbllo);
    cudaGetSymbolAddress((void**)&yhi,    g_yhi);    cudaGetSymbolAddress((void**)&ylo,    g_ylo);
    cudaGetSymbolAddress((void**)&xlnhi,  g_xlnhi);  cudaGetSymbolAddress((void**)&xlnlo,  g_xlnlo);
    cudaGetSymbolAddress((void**)&winhi,  g_winhi);  cudaGetSymbolAddress((void**)&winlo,  g_winlo);
    cudaGetSymbolAddress((void**)&wxhi,   g_wxhi);   cudaGetSymbolAddress((void**)&wxlo,   g_wxlo);
    cudaGetSymbolAddress((void**)&wdthi,  g_wdthi);  cudaGetSymbolAddress((void**)&wdtlo,  g_wdtlo);
    cudaGetSymbolAddress((void**)&wouthi, g_wouthi); cudaGetSymbolAddress((void**)&woutlo, g_woutlo);
    cudaGetSymbolAddress((void**)&wheadhi,g_wheadhi);cudaGetSymbolAddress((void**)&wheadlo,g_wheadlo);

    set_smem((const void*)mma_gemm<0>, SMB);
    set_smem((const void*)mma_gemm<1>, SMB);
    set_smem((const void*)mma_gemm<2>, SMB);

    // ---- launch order: ncu (-s 5 -c 1) captures kernel_launch index 3 ----
    // [0] embed  [1] W_in split  [2] merged split4  [3] xz GEMM (profiled)
    embed_kernel<<<(MROWS * DIMM + 255) / 256, 256>>>(ids, emb, xhi, xlo);

    {
        int n = 4 * 2 * DINNER * DIMM;
        split_kernel<<<(n/4+255)/256,256>>>(W_in, winhi, winlo, n/4);
        int n0 = (4 * DBLCOLS * DINNER) / 4;
        int n1 = (4 * DINNER * DTRANK) / 4;
        int n2 = (4 * DIMM * DINNER) / 4;
        int n3 = (VOCAB * DIMM) / 4;
        split4_kernel<<<(n0+n1+n2+n3+255)/256,256>>>(
            W_x,   wxhi,   wxlo,   n0,
            W_dt,  wdthi,  wdtlo,  n1,
            W_out, wouthi, woutlo, n2,
            W_head,wheadhi,wheadlo,n3);
    }

    for (int i = 0; i < 4; ++i) {
        // xz = x @ W_in^T : [4096, 3072], K=768
        mma_gemm<0><<<dim3((2*DINNER)/96, MROWS/128), 128, SMB>>>(
            MROWS, 2*DINNER, DIMM,
            xhi, xlo, DIMM,
            winhi + (size_t)i * 2*DINNER*DIMM, winlo + (size_t)i * 2*DINNER*DIMM, DIMM,
            nullptr, xz, 2*DINNER, nullptr, nullptr);

        conv_silu_kernel<<<(MROWS * DINNER + 255) / 256, 256>>>(
            xz, conv_w + (size_t)i * DINNER * DCONV, conv_b + (size_t)i * DINNER,
            xssm, xshi, xslo);

        // dbl partials: x_ssm @ W_x^T split-K (K = 1536 -> 4 x 384)
        mma_gemm<0><<<dim3(1, MROWS/128, KSPLIT), 128, SMB>>>(
            MROWS, DBLCOLS, DINNER / KSPLIT,
            xshi, xslo, DINNER,
            wxhi + (size_t)i * DBLCOLS * DINNER, wxlo + (size_t)i * DBLCOLS * DINNER, DINNER,
            nullptr, dblp, DBLCOLS, nullptr, nullptr);
        dbl_reduce_kernel<<<(MROWS * DBLCOLS + 255) / 256, 256>>>(dblp, dbl, dblhi, dbllo);

        // dt = softplus(dbl[:, :48] @ W_dt^T + b_dt) : [4096, 1536], K=48
        mma_gemm<1><<<dim3(DINNER/96, MROWS/128), 128, SMB>>>(
            MROWS, DINNER, DTRANK,
            dblhi, dbllo, DBLCOLS,
            wdthi + (size_t)i * DINNER * DTRANK, wdtlo + (size_t)i * DINNER * DTRANK, DTRANK,
            b_dt + (size_t)i * DINNER, dt, DINNER, nullptr, nullptr);

        const float* Al = A_log + (size_t)i * DINNER * DSTATE;
        scan_phase1<<<(NCHUNK * NCH) / 256, 256>>>(dt, xssm, dbl, Al, he, pe);
        scan_phase2<<<NCH / 256, 256>>>(he, pe, hh);
        scan_phase3<<<(NCHUNK * NCH) / 256, 256>>>(dt, xssm, dbl, Al, hh,
                                                   Dp + (size_t)i * DINNER, xz, yhi, ylo);

        // x = y @ W_out^T : [4096, 768], K=1536
        mma_gemm<2><<<dim3(DIMM/96, MROWS/128), 128, SMB>>>(
            MROWS, DIMM, DINNER,
            yhi, ylo, DINNER,
            wouthi + (size_t)i * DIMM * DINNER, woutlo + (size_t)i * DIMM * DINNER, DINNER,
            nullptr, x, DIMM, xhi, xlo);
    }

    layernorm_kernel<<<MROWS, 256>>>(x, ln_g, ln_b, xlnhi, xlnlo);

    // logits = x_ln @ W_head^T : [4096, 32000], K=768
    mma_gemm<0><<<dim3((VOCAB + 95)/96, MROWS/128), 128, SMB>>>(
        MROWS, VOCAB, DIMM,
        xlnhi, xlnlo, DIMM,
        wheadhi, wheadlo, DIMM,
        nullptr, logits, VOCAB, nullptr, nullptr);
}